// round 6
// baseline (speedup 1.0000x reference)
#include <cuda_runtime.h>
#include <cstdint>

// out[dst[e], :] += w[e] * x[src[e], :]   — via CSR-by-dst build + per-node gather.
// x: [N, 64] f32; edge_weight: [E] f32; edge_index: [2, E] int32; out: [N, 64] f32

static constexpr int F = 64;
static constexpr int THREADS = 256;
static constexpr int N_MAX = 1 << 17;   // 131072 >= 100000
static constexpr int E_MAX = 1 << 21;   // 2M >= 1M

// Scratch (static device globals: allocation-free).
__device__ int g_count[N_MAX];
__device__ int g_offset[N_MAX];
__device__ int g_cursor[N_MAX];
__device__ int g_bsums[256];
__device__ unsigned long long g_sw[E_MAX];   // packed (w_bits<<32) | src

// ---------- 1. zero counters ----------
__global__ void k_zero(int n) {
    int i = blockIdx.x * blockDim.x + threadIdx.x;
    if (i < n) { g_count[i] = 0; g_cursor[i] = 0; }
}

// ---------- 2. histogram of dst ----------
__global__ void k_hist(const int* __restrict__ ei, int E) {
    int e = blockIdx.x * blockDim.x + threadIdx.x;
    if (e < E) atomicAdd(&g_count[__ldcs(&ei[E + e])], 1);
}

// ---------- 3a. block-level exclusive scan (1024 elems/block) ----------
__global__ void k_scan1(int n) {
    __shared__ int tmp[1024];
    int gid = blockIdx.x * 1024 + threadIdx.x;
    int v = (gid < n) ? g_count[gid] : 0;
    tmp[threadIdx.x] = v;
    __syncthreads();
    for (int d = 1; d < 1024; d <<= 1) {
        int t = (threadIdx.x >= d) ? tmp[threadIdx.x - d] : 0;
        __syncthreads();
        tmp[threadIdx.x] += t;
        __syncthreads();
    }
    if (gid < n) g_offset[gid] = tmp[threadIdx.x] - v;      // exclusive
    if (threadIdx.x == 1023) g_bsums[blockIdx.x] = tmp[1023];
}

// ---------- 3b. scan of block sums (single block, up to 256) ----------
__global__ void k_scan2(int nblocks) {
    __shared__ int tmp[256];
    int v = (threadIdx.x < nblocks) ? g_bsums[threadIdx.x] : 0;
    tmp[threadIdx.x] = v;
    __syncthreads();
    for (int d = 1; d < 256; d <<= 1) {
        int t = (threadIdx.x >= d) ? tmp[threadIdx.x - d] : 0;
        __syncthreads();
        tmp[threadIdx.x] += t;
        __syncthreads();
    }
    if (threadIdx.x < nblocks) g_bsums[threadIdx.x] = tmp[threadIdx.x] - v;  // exclusive
}

// ---------- 3c. add block bases ----------
__global__ void k_scan3(int n) {
    int gid = blockIdx.x * 1024 + threadIdx.x;
    if (gid < n) g_offset[gid] += g_bsums[blockIdx.x];
}

// ---------- 4. bin edges by dst ----------
__global__ void k_binplace(const float* __restrict__ ew,
                           const int* __restrict__ ei, int E) {
    int e = blockIdx.x * blockDim.x + threadIdx.x;
    if (e >= E) return;
    int s = __ldcs(&ei[e]);
    int d = __ldcs(&ei[E + e]);
    float w = __ldcs(&ew[e]);
    int pos = g_offset[d] + atomicAdd(&g_cursor[d], 1);
    g_sw[pos] = ((unsigned long long)__float_as_uint(w) << 32) | (unsigned int)s;
}

// ---------- 5. per-node gather: warp per node, float2 per lane ----------
__global__ void __launch_bounds__(THREADS)
k_gather(const float* __restrict__ x, float* __restrict__ out, int N) {
    int warp = (blockIdx.x * THREADS + threadIdx.x) >> 5;
    int lane = threadIdx.x & 31;
    if (warp >= N) return;

    int off = g_offset[warp];
    int deg = g_count[warp];
    const unsigned long long* sw = g_sw + off;

    float2 acc = make_float2(0.f, 0.f);
    int co = lane * 2;

    int j = 0;
    for (; j + 2 <= deg; j += 2) {
        // Two independent chains (broadcast sw loads, coalesced 256B row loads).
        unsigned long long a = __ldg(&sw[j]);
        unsigned long long b = __ldg(&sw[j + 1]);
        int   s0 = (int)(unsigned int)a;
        int   s1 = (int)(unsigned int)b;
        float w0 = __uint_as_float((unsigned int)(a >> 32));
        float w1 = __uint_as_float((unsigned int)(b >> 32));
        float2 v0 = __ldg(reinterpret_cast<const float2*>(x + (long long)s0 * F + co));
        float2 v1 = __ldg(reinterpret_cast<const float2*>(x + (long long)s1 * F + co));
        acc.x += w0 * v0.x; acc.y += w0 * v0.y;
        acc.x += w1 * v1.x; acc.y += w1 * v1.y;
    }
    if (j < deg) {
        unsigned long long a = __ldg(&sw[j]);
        int   s0 = (int)(unsigned int)a;
        float w0 = __uint_as_float((unsigned int)(a >> 32));
        float2 v0 = __ldg(reinterpret_cast<const float2*>(x + (long long)s0 * F + co));
        acc.x += w0 * v0.x; acc.y += w0 * v0.y;
    }

    *reinterpret_cast<float2*>(out + (long long)warp * F + co) = acc;
}

extern "C" void kernel_launch(void* const* d_in, const int* in_sizes, int n_in,
                              void* d_out, int out_size)
{
    const float* x  = (const float*)d_in[0];
    const float* ew = (const float*)d_in[1];
    const int*   ei = (const int*)d_in[2];
    float* out = (float*)d_out;

    int E = in_sizes[2] / 2;
    int N = out_size / F;
    if (E > E_MAX || N > N_MAX) return;   // fixed problem sizes: 1M / 100k

    int nscan = (N + 1023) / 1024;        // blocks in level-1 scan (<=128)

    k_zero    <<<(N + THREADS - 1) / THREADS, THREADS>>>(N);
    k_hist    <<<(E + THREADS - 1) / THREADS, THREADS>>>(ei, E);
    k_scan1   <<<nscan, 1024>>>(N);
    k_scan2   <<<1, 256>>>(nscan);
    k_scan3   <<<nscan, 1024>>>(N);
    k_binplace<<<(E + THREADS - 1) / THREADS, THREADS>>>(ew, ei, E);

    int warps = N;                        // one warp per node
    int blocks = (warps * 32 + THREADS - 1) / THREADS;
    k_gather  <<<blocks, THREADS>>>(x, out, N);
}

// round 7
// speedup vs baseline: 1.1678x; 1.1678x over previous
#include <cuda_runtime.h>
#include <cstdint>

// out[dst[e], :] += w[e] * x[src[e], :]
// Strategy: fixed-capacity dst-binning (no scan), then per-node register-accumulated
// gather writing each output row exactly once. Overflow (impossible for the given
// random graph, P~1e-36) handled by an atomic fallback kernel for correctness.

static constexpr int F = 64;
static constexpr int THREADS = 256;
static constexpr int N_MAX = 1 << 17;       // 131072 >= 100000
static constexpr int E_MAX = 1 << 21;       // 2M >= 1M
static constexpr int MAX_DEG = 64;          // Poisson(10) tail safety

// Scratch (static device globals: allocation-free).
__device__ int g_cursor[N_MAX + 1];                       // [N_MAX] = overflow count
__device__ unsigned long long g_sw[(size_t)N_MAX * MAX_DEG]; // packed (w<<32)|src per dst-bin
__device__ int g_ovf[E_MAX];                              // overflowed edge ids

// ---------- 1. bin edges by dst (int4-vectorized, 4 edges/thread) ----------
__global__ void __launch_bounds__(THREADS)
k_binplace(const float* __restrict__ ew, const int* __restrict__ ei, int E)
{
    int t = blockIdx.x * THREADS + threadIdx.x;
    int quads = E >> 2;
    if (t < quads) {
        int e0 = t * 4;
        int4   s4 = __ldcs(reinterpret_cast<const int4*>(ei + e0));
        int4   d4 = __ldcs(reinterpret_cast<const int4*>(ei + E + e0));
        float4 w4 = __ldcs(reinterpret_cast<const float4*>(ew + e0));
        #pragma unroll
        for (int k = 0; k < 4; k++) {
            int s = (k == 0) ? s4.x : (k == 1) ? s4.y : (k == 2) ? s4.z : s4.w;
            int d = (k == 0) ? d4.x : (k == 1) ? d4.y : (k == 2) ? d4.z : d4.w;
            float w = (k == 0) ? w4.x : (k == 1) ? w4.y : (k == 2) ? w4.z : w4.w;
            int c = atomicAdd(&g_cursor[d], 1);
            if (c < MAX_DEG)
                g_sw[(size_t)d * MAX_DEG + c] =
                    ((unsigned long long)__float_as_uint(w) << 32) | (unsigned int)s;
            else
                g_ovf[atomicAdd(&g_cursor[N_MAX], 1)] = e0 + k;
        }
    } else {
        // tail edges (E not multiple of 4)
        int e = quads * 4 + (t - quads);
        if (e < E) {
            int s = __ldg(&ei[e]);
            int d = __ldg(&ei[E + e]);
            float w = __ldg(&ew[e]);
            int c = atomicAdd(&g_cursor[d], 1);
            if (c < MAX_DEG)
                g_sw[(size_t)d * MAX_DEG + c] =
                    ((unsigned long long)__float_as_uint(w) << 32) | (unsigned int)s;
            else
                g_ovf[atomicAdd(&g_cursor[N_MAX], 1)] = e;
        }
    }
}

// ---------- 2. per-node gather: one warp per node, float2 per lane ----------
__global__ void __launch_bounds__(THREADS)
k_gather(const float* __restrict__ x, float* __restrict__ out, int N)
{
    int warp = (blockIdx.x * THREADS + threadIdx.x) >> 5;
    int lane = threadIdx.x & 31;
    if (warp >= N) return;

    int deg = g_cursor[warp];
    if (deg > MAX_DEG) deg = MAX_DEG;
    const unsigned long long* sw = g_sw + (size_t)warp * MAX_DEG;

    float2 acc = make_float2(0.f, 0.f);
    int co = lane * 2;

    int j = 0;
    for (; j + 4 <= deg; j += 4) {
        // 32B-aligned slot loads (bin base 512B-aligned, j multiple of 4).
        ulonglong2 p0 = __ldg(reinterpret_cast<const ulonglong2*>(sw + j));
        ulonglong2 p1 = __ldg(reinterpret_cast<const ulonglong2*>(sw + j + 2));
        int   s0 = (int)(unsigned int)p0.x, s1 = (int)(unsigned int)p0.y;
        int   s2 = (int)(unsigned int)p1.x, s3 = (int)(unsigned int)p1.y;
        float w0 = __uint_as_float((unsigned int)(p0.x >> 32));
        float w1 = __uint_as_float((unsigned int)(p0.y >> 32));
        float w2 = __uint_as_float((unsigned int)(p1.x >> 32));
        float w3 = __uint_as_float((unsigned int)(p1.y >> 32));
        // 4 independent row loads (MLP=4), each fully coalesced 256B warp-wide.
        float2 v0 = __ldg(reinterpret_cast<const float2*>(x + (long long)s0 * F + co));
        float2 v1 = __ldg(reinterpret_cast<const float2*>(x + (long long)s1 * F + co));
        float2 v2 = __ldg(reinterpret_cast<const float2*>(x + (long long)s2 * F + co));
        float2 v3 = __ldg(reinterpret_cast<const float2*>(x + (long long)s3 * F + co));
        acc.x += w0 * v0.x; acc.y += w0 * v0.y;
        acc.x += w1 * v1.x; acc.y += w1 * v1.y;
        acc.x += w2 * v2.x; acc.y += w2 * v2.y;
        acc.x += w3 * v3.x; acc.y += w3 * v3.y;
    }
    for (; j < deg; j++) {
        unsigned long long a = __ldg(&sw[j]);
        int   s = (int)(unsigned int)a;
        float w = __uint_as_float((unsigned int)(a >> 32));
        float2 v = __ldg(reinterpret_cast<const float2*>(x + (long long)s * F + co));
        acc.x += w * v.x; acc.y += w * v.y;
    }

    *reinterpret_cast<float2*>(out + (long long)warp * F + co) = acc;  // single write, no memset needed
}

// ---------- 3. overflow fallback (normally count==0: immediate exit) ----------
__global__ void __launch_bounds__(THREADS)
k_fallback(const float* __restrict__ x, const float* __restrict__ ew,
           const int* __restrict__ ei, float* __restrict__ out, int E)
{
    int n = g_cursor[N_MAX] * 16;
    for (int i = blockIdx.x * THREADS + threadIdx.x; i < n; i += gridDim.x * THREADS) {
        int e = g_ovf[i >> 4];
        int c = i & 15;
        int   s = __ldg(&ei[e]);
        int   d = __ldg(&ei[E + e]);
        float w = __ldg(&ew[e]);
        float4 v = __ldg(reinterpret_cast<const float4*>(x + (long long)s * F + c * 4));
        v.x *= w; v.y *= w; v.z *= w; v.w *= w;
        float* dp = out + (long long)d * F + c * 4;
        asm volatile("red.global.add.v4.f32 [%0], {%1, %2, %3, %4};"
                     :: "l"(dp), "f"(v.x), "f"(v.y), "f"(v.z), "f"(v.w) : "memory");
    }
}

extern "C" void kernel_launch(void* const* d_in, const int* in_sizes, int n_in,
                              void* d_out, int out_size)
{
    const float* x  = (const float*)d_in[0];
    const float* ew = (const float*)d_in[1];
    const int*   ei = (const int*)d_in[2];
    float* out = (float*)d_out;

    int E = in_sizes[2] / 2;
    int N = out_size / F;
    if (E > E_MAX || N > N_MAX) return;   // fixed problem: E=1M, N=100k

    void* cur_addr = nullptr;
    cudaGetSymbolAddress(&cur_addr, g_cursor);
    cudaMemsetAsync(cur_addr, 0, (size_t)(N_MAX + 1) * sizeof(int), 0);

    int bin_threads = (E >> 2) + (E & 3);
    k_binplace<<<(bin_threads + THREADS - 1) / THREADS, THREADS>>>(ew, ei, E);

    int blocks = (N * 32 + THREADS - 1) / THREADS;
    k_gather<<<blocks, THREADS>>>(x, out, N);

    k_fallback<<<32, THREADS>>>(x, ew, ei, out, E);
}